// round 14
// baseline (speedup 1.0000x reference)
#include <cuda_runtime.h>
#include <cuda_bf16.h>

// ---------------- problem constants ----------------
#define BB     2
#define LLEN   2048
#define DMODEL 1536
#define HH     12
#define FDIM   16
#define DVDIM  128
#define D2     256
#define CH     128
#define NC     16
#define NTOK   4096
#define QKDIM  192
#define LN_EPS 1e-5f
#define EPS    1e-12f
#define MKS    40                  // MK tile k-stride (bf16)
#define KNS    136                 // KN tile n-stride, 128-wide tiles
#define KNSA   72                  // KN tile stride for 64-wide kvstate A tiles
#define ABY2   (64 * MKS * 2)      // 5120  MK buffer (64 rows)
#define BBYT   (32 * KNS * 2)      // 8704  KN buffer (128 wide)
#define ABYK   (32 * KNSA * 2)     // 4608  KN buffer (64 wide)
#define GST2   (2 * ABY2 + 2 * BBYT)   // 27648 proj/attn_b stage
#define KST2   (2 * ABYK + 2 * BBYT)   // 26624 kvstate stage

typedef __nv_bfloat16 bf16;

// ---------------- scratch (device globals) ----------------
__device__ float g_q  [NTOK * QKDIM];
__device__ float g_k  [NTOK * QKDIM];
__device__ float g_v  [(size_t)NTOK * DMODEL];
__device__ float g_S  [(size_t)BB * HH * NC * D2 * DVDIM];
__device__ float g_z  [(size_t)BB * HH * NC * D2];
__device__ float g_A  [(size_t)BB * HH * NC * CH * CH];
__device__ float g_den[(size_t)BB * HH * NC * CH];
__device__ float g_oh [(size_t)NTOK * DMODEL];

// ---------------- helpers ----------------
__device__ __forceinline__ unsigned sptr(const void* p) {
    return (unsigned)__cvta_generic_to_shared(p);
}
__device__ __forceinline__ void split2(float x, float y, unsigned& h, unsigned& l) {
    __nv_bfloat162 hh = __floats2bfloat162_rn(x, y);
    float rx = x - __low2float(hh);
    float ry = y - __high2float(hh);
    __nv_bfloat162 ll = __floats2bfloat162_rn(rx, ry);
    h = *reinterpret_cast<unsigned*>(&hh);
    l = *reinterpret_cast<unsigned*>(&ll);
}
__device__ __forceinline__ void split8(const float* v, uint4& h, uint4& l) {
    split2(v[0], v[1], h.x, l.x);
    split2(v[2], v[3], h.y, l.y);
    split2(v[4], v[5], h.z, l.z);
    split2(v[6], v[7], h.w, l.w);
}
__device__ __forceinline__ void mma16(float* c, const unsigned* a, const unsigned* b) {
    asm volatile("mma.sync.aligned.m16n8k16.row.col.f32.bf16.bf16.f32 "
        "{%0,%1,%2,%3},{%4,%5,%6,%7},{%8,%9},{%0,%1,%2,%3};"
        : "+f"(c[0]), "+f"(c[1]), "+f"(c[2]), "+f"(c[3])
        : "r"(a[0]), "r"(a[1]), "r"(a[2]), "r"(a[3]), "r"(b[0]), "r"(b[1]));
}
__device__ __forceinline__ void ldsm4(uint4& r, unsigned a) {
    asm volatile("ldmatrix.sync.aligned.m8n8.x4.shared.b16 {%0,%1,%2,%3},[%4];"
        : "=r"(r.x), "=r"(r.y), "=r"(r.z), "=r"(r.w) : "r"(a));
}
__device__ __forceinline__ void ldsm4t(uint4& r, unsigned a) {
    asm volatile("ldmatrix.sync.aligned.m8n8.x4.trans.shared.b16 {%0,%1,%2,%3},[%4];"
        : "=r"(r.x), "=r"(r.y), "=r"(r.z), "=r"(r.w) : "r"(a));
}
__device__ __forceinline__ void tile3(float* acc, const uint4& ah, const uint4& al,
                                      unsigned bh0, unsigned bh1, unsigned bl0, unsigned bl1) {
    unsigned A[4] = {ah.x, ah.y, ah.z, ah.w};
    unsigned L[4] = {al.x, al.y, al.z, al.w};
    unsigned BH[2] = {bh0, bh1}, BL[2] = {bl0, bl1};
    mma16(acc, A, BH);
    mma16(acc, L, BH);
    mma16(acc, A, BL);
}

// One BK=32 stage via ldmatrix, warp tile 32x32 (2 m-tiles x 4 n-tiles).
// AO/AMT parametrize the A-operand layout stride; ATR selects .trans.
template<int AO, int AMT, bool ATR>
__device__ __forceinline__ void mma_stage(unsigned fAh, unsigned fAl,
                                          unsigned fBh, unsigned fBl,
                                          float (*acc)[4]) {
#pragma unroll
    for (int o = 0; o < 2; ++o) {
        uint4 ah[2], al[2], bh[2], bl[2];
#pragma unroll
        for (int mt = 0; mt < 2; ++mt) {
            if (ATR) { ldsm4t(ah[mt], fAh + o * AO + mt * AMT); ldsm4t(al[mt], fAl + o * AO + mt * AMT); }
            else     { ldsm4 (ah[mt], fAh + o * AO + mt * AMT); ldsm4 (al[mt], fAl + o * AO + mt * AMT); }
        }
#pragma unroll
        for (int p = 0; p < 2; ++p) {
            ldsm4t(bh[p], fBh + o * 4352 + p * 32);
            ldsm4t(bl[p], fBl + o * 4352 + p * 32);
        }
#pragma unroll
        for (int mt = 0; mt < 2; ++mt)
#pragma unroll
            for (int p = 0; p < 2; ++p) {
                tile3(acc[mt * 4 + 2 * p],     ah[mt], al[mt], bh[p].x, bh[p].y, bl[p].x, bl[p].y);
                tile3(acc[mt * 4 + 2 * p + 1], ah[mt], al[mt], bh[p].z, bh[p].w, bl[p].z, bl[p].w);
            }
    }
}

// ---------------- projection GEMM core: 64x128 block, 256 thr -----------
__device__ __forceinline__ void gemm_core(const float* __restrict__ A,
                                          const float* __restrict__ B,
                                          float* __restrict__ C,
                                          int N, int K, int m0, int n0, char* sm) {
    const unsigned smb = sptr(sm);
    const int tid = threadIdx.x, lane = tid & 31, w = tid >> 5;
    const int g = lane >> 2, t = lane & 3;
    const int mbase = (w & 1) * 32, nbase = (w >> 1) * 32;
    const int arow = tid >> 2, kseg = (tid & 3) * 8;     // A: 64x32, 8/thr
    const int krow = tid >> 3, nseg = (tid & 7) * 16;    // B: 32x128, 16/thr
    const bool bval = (n0 + nseg) < N;
    const unsigned offA = ((mbase + (lane & 15)) * MKS + (lane >> 4) * 8) * 2;
    const unsigned offB = ((((lane >> 3) & 1) * 8 + (lane & 7)) * KNS + nbase + ((lane >> 4) & 1) * 8) * 2;

    float acc[8][4];
#pragma unroll
    for (int i = 0; i < 8; ++i) acc[i][0] = acc[i][1] = acc[i][2] = acc[i][3] = 0.f;

    float4 ra[2], rb[4];
    auto loadRegs = [&](int k0) {
        ra[0] = *(const float4*)(A + (size_t)(m0 + arow) * K + k0 + kseg);
        ra[1] = *(const float4*)(A + (size_t)(m0 + arow) * K + k0 + kseg + 4);
        if (bval) {
            const float* bp = B + (size_t)(k0 + krow) * N + n0 + nseg;
            rb[0] = *(const float4*)bp;       rb[1] = *(const float4*)(bp + 4);
            rb[2] = *(const float4*)(bp + 8); rb[3] = *(const float4*)(bp + 12);
        } else {
            rb[0] = rb[1] = rb[2] = rb[3] = make_float4(0.f, 0.f, 0.f, 0.f);
        }
    };
    auto storeStage = [&](int bsel) {
        bf16* Ah = (bf16*)(sm + bsel * GST2);
        bf16* Al = (bf16*)(sm + bsel * GST2 + ABY2);
        bf16* Bh = (bf16*)(sm + bsel * GST2 + 2 * ABY2);
        bf16* Bl = (bf16*)(sm + bsel * GST2 + 2 * ABY2 + BBYT);
        uint4 h4, l4;
        split8((const float*)&ra[0], h4, l4);
        *(uint4*)(Ah + arow * MKS + kseg) = h4;
        *(uint4*)(Al + arow * MKS + kseg) = l4;
        split8((const float*)&rb[0], h4, l4);
        *(uint4*)(Bh + krow * KNS + nseg) = h4;
        *(uint4*)(Bl + krow * KNS + nseg) = l4;
        split8((const float*)&rb[2], h4, l4);
        *(uint4*)(Bh + krow * KNS + nseg + 8) = h4;
        *(uint4*)(Bl + krow * KNS + nseg + 8) = l4;
    };

    const int NSt = K >> 5;
    loadRegs(0);
    storeStage(0);
    loadRegs(32);
    __syncthreads();
    for (int s = 0; s < NSt; ++s) {
        const unsigned sb = smb + (s & 1) * GST2;
        mma_stage<32, 1280, false>(sb + offA, sb + ABY2 + offA,
                                   sb + 2 * ABY2 + offB, sb + 2 * ABY2 + BBYT + offB, acc);
        if (s + 1 < NSt) {
            storeStage((s + 1) & 1);
            if (s + 2 < NSt) loadRegs((s + 2) * 32);
        }
        __syncthreads();
    }
#pragma unroll
    for (int mt = 0; mt < 2; ++mt) {
        const int r0 = m0 + mbase + mt * 16 + g;
#pragma unroll
        for (int nt = 0; nt < 4; ++nt) {
            const int col = n0 + nbase + nt * 8 + t * 2;
            if (col < N) {
                const float* a4 = acc[mt * 4 + nt];
                *(float2*)(C + (size_t)r0 * N + col)       = make_float2(a4[0], a4[1]);
                *(float2*)(C + (size_t)(r0 + 8) * N + col) = make_float2(a4[2], a4[3]);
            }
        }
    }
}

__global__ __launch_bounds__(256) void projqk_kernel(const float* __restrict__ x,
                                                     const float* __restrict__ Wq,
                                                     const float* __restrict__ Wk) {
    extern __shared__ char sm[];
    const float* B = blockIdx.z ? Wk : Wq;
    float* C = blockIdx.z ? (float*)g_k : (float*)g_q;
    gemm_core(x, B, C, QKDIM, DMODEL, blockIdx.y * 64, blockIdx.x * 128, sm);
}

__global__ __launch_bounds__(256) void proj_kernel(const float* __restrict__ A,
                                                   const float* __restrict__ B,
                                                   float* __restrict__ C, int N, int K) {
    extern __shared__ char sm[];
    gemm_core(A, B, C, N, K, blockIdx.y * 64, blockIdx.x * 128, sm);
}

// ---------------- LayerNorm over 192 dims, in place ----------------
__global__ __launch_bounds__(256) void ln_kernel(const float* __restrict__ gq,
                                                 const float* __restrict__ bq,
                                                 const float* __restrict__ gk,
                                                 const float* __restrict__ bk) {
    const int warp = (blockIdx.x * blockDim.x + threadIdx.x) >> 5;
    const int lane = threadIdx.x & 31;
    if (warp >= 2 * NTOK) return;
    const bool isq = warp < NTOK;
    float* p = isq ? (g_q + (size_t)warp * QKDIM) : (g_k + (size_t)(warp - NTOK) * QKDIM);
    const float* gg = isq ? gq : gk;
    const float* bb = isq ? bq : bk;
    float x[6]; float s = 0.f, s2 = 0.f;
#pragma unroll
    for (int i = 0; i < 6; ++i) { x[i] = p[lane + 32 * i]; s += x[i]; s2 = fmaf(x[i], x[i], s2); }
#pragma unroll
    for (int o = 16; o > 0; o >>= 1) {
        s += __shfl_xor_sync(0xffffffffu, s, o);
        s2 += __shfl_xor_sync(0xffffffffu, s2, o);
    }
    const float mu = s * (1.f / QKDIM);
    const float var = s2 * (1.f / QKDIM) - mu * mu;
    const float r = rsqrtf(var + LN_EPS);
#pragma unroll
    for (int i = 0; i < 6; ++i) {
        const int c = lane + 32 * i;
        p[c] = (x[i] - mu) * r * gg[c] + bb[c];
    }
}

// ---------------- per-chunk state: S_c = k2_c^T v_c, z_c = sum k2_c ------
// 64(d) x 128(v) block, 256 thr. grid = B*H*NC*4 (d quarters).
__global__ __launch_bounds__(256) void kvstate_db() {
    extern __shared__ char sm[];
    const unsigned smb = sptr(sm);
    float* ksm = (float*)(sm + 2 * KST2);     // 128*17 fp32
    const int gx = blockIdx.x;
    const int dq = gx & 3, rest = gx >> 2;
    const int ch = rest & (NC - 1), bh = rest >> 4;
    const int b = bh / HH, h = bh % HH;
    const int d0 = dq * 64;
    const int tid = threadIdx.x, lane = tid & 31, w = tid >> 5;
    const int g = lane >> 2, t = lane & 3;
    const int mbase = (w & 1) * 32, nbase = (w >> 1) * 32;
    const int pcA = tid >> 3, egA = (tid & 7) * 8;   // A gen: 32 c-rows x 64 d
    const int krow = tid >> 3, nseg = (tid & 7) * 16; // B: 32 c-rows x 128 v

    const float* kb = g_k + (size_t)(b * LLEN + ch * CH) * QKDIM + h * FDIM;
    const float* vb = g_v + (size_t)(b * LLEN + ch * CH) * DMODEL + h * DVDIM;

    {   // load k tile 128x16 (8 floats/thread)
        const int r = tid >> 1, c8 = (tid & 1) * 8;
        float4 k0 = *(const float4*)(kb + (size_t)r * QKDIM + c8);
        float4 k1 = *(const float4*)(kb + (size_t)r * QKDIM + c8 + 4);
        ksm[r * 17 + c8 + 0] = k0.x; ksm[r * 17 + c8 + 1] = k0.y;
        ksm[r * 17 + c8 + 2] = k0.z; ksm[r * 17 + c8 + 3] = k0.w;
        ksm[r * 17 + c8 + 4] = k1.x; ksm[r * 17 + c8 + 5] = k1.y;
        ksm[r * 17 + c8 + 6] = k1.z; ksm[r * 17 + c8 + 7] = k1.w;
    }

    const int iA = (d0 + egA) >> 4, jb = egA & 15;
    const unsigned offA = ((((lane >> 4) & 1) * 8 + (lane & 7)) * KNSA + mbase + ((lane >> 3) & 1) * 8) * 2;
    const unsigned offB = ((((lane >> 3) & 1) * 8 + (lane & 7)) * KNS + nbase + ((lane >> 4) & 1) * 8) * 2;

    float acc[8][4];
#pragma unroll
    for (int i = 0; i < 8; ++i) acc[i][0] = acc[i][1] = acc[i][2] = acc[i][3] = 0.f;
    float zacc[8];
#pragma unroll
    for (int e = 0; e < 8; ++e) zacc[e] = 0.f;

    float vA[16];
    auto loadV = [&](int c0) {
        const float* r0p = vb + (size_t)(c0 + krow) * DMODEL + nseg;
        *(float4*)&vA[0]  = *(const float4*)r0p;
        *(float4*)&vA[4]  = *(const float4*)(r0p + 4);
        *(float4*)&vA[8]  = *(const float4*)(r0p + 8);
        *(float4*)&vA[12] = *(const float4*)(r0p + 12);
    };
    auto stage = [&](int bsel, int c0) {
        bf16* Ah = (bf16*)(sm + bsel * KST2);
        bf16* Al = (bf16*)(sm + bsel * KST2 + ABYK);
        bf16* Bh = (bf16*)(sm + bsel * KST2 + 2 * ABYK);
        bf16* Bl = (bf16*)(sm + bsel * KST2 + 2 * ABYK + BBYT);
        const int ca = c0 + pcA;
        float pa[8];
        const float kia = ksm[ca * 17 + iA] * 0.25f;
#pragma unroll
        for (int e = 0; e < 8; ++e) {
            pa[e] = kia * ksm[ca * 17 + jb + e];
            zacc[e] += pa[e];
        }
        uint4 h4, l4;
        split8(pa, h4, l4);
        *(uint4*)(Ah + pcA * KNSA + egA) = h4;
        *(uint4*)(Al + pcA * KNSA + egA) = l4;
        split8(vA, h4, l4);
        *(uint4*)(Bh + krow * KNS + nseg) = h4;
        *(uint4*)(Bl + krow * KNS + nseg) = l4;
        split8(vA + 8, h4, l4);
        *(uint4*)(Bh + krow * KNS + nseg + 8) = h4;
        *(uint4*)(Bl + krow * KNS + nseg + 8) = l4;
    };

    loadV(0);
    __syncthreads();            // ksm visible
    stage(0, 0);
    loadV(32);
    __syncthreads();
    for (int s = 0; s < 4; ++s) {
        const unsigned sb = smb + (s & 1) * KST2;
        mma_stage<2304, 32, true>(sb + offA, sb + ABYK + offA,
                                  sb + 2 * ABYK + offB, sb + 2 * ABYK + BBYT + offB, acc);
        if (s + 1 < 4) {
            stage((s + 1) & 1, (s + 1) * 32);
            if (s + 2 < 4) loadV((s + 2) * 32);
        }
        __syncthreads();
    }

    float* Sout = g_S + (((size_t)bh * NC + ch) * D2 + d0) * DVDIM;
#pragma unroll
    for (int mt = 0; mt < 2; ++mt) {
        const int r0 = mbase + mt * 16 + g;
#pragma unroll
        for (int nt = 0; nt < 4; ++nt) {
            const int col = nbase + nt * 8 + t * 2;
            const float* a4 = acc[mt * 4 + nt];
            *(float2*)(Sout + (size_t)r0 * DVDIM + col)       = make_float2(a4[0], a4[1]);
            *(float2*)(Sout + (size_t)(r0 + 8) * DVDIM + col) = make_float2(a4[2], a4[3]);
        }
    }
    // z reduction via buffer 0 (last read at s=2, already synced)
    float* zred = (float*)sm;   // [32][64]
#pragma unroll
    for (int e = 0; e < 8; ++e) zred[pcA * 64 + egA + e] = zacc[e];
    __syncthreads();
    if (tid < 64) {
        float z = 0.f;
#pragma unroll
        for (int p = 0; p < 32; ++p) z += zred[p * 64 + tid];
        g_z[((size_t)bh * NC + ch) * D2 + d0 + tid] = z;
    }
}

// ---------------- exclusive prefix over chunks ----------------
__global__ __launch_bounds__(256) void prefix_kernel() {
    const int NS = BB * HH * D2 * DVDIM;
    const int NZ = BB * HH * D2;
    const int idx = blockIdx.x * blockDim.x + threadIdx.x;
    if (idx < NS) {
        const int bh = idx / (D2 * DVDIM);
        const int rem = idx % (D2 * DVDIM);
        const size_t base = (size_t)bh * NC * D2 * DVDIM + rem;
        float run = 0.f;
#pragma unroll
        for (int c = 0; c < NC; ++c) {
            const size_t p = base + (size_t)c * (D2 * DVDIM);
            const float t2 = g_S[p]; g_S[p] = run; run += t2;
        }
    } else if (idx < NS + NZ) {
        const int j = idx - NS;
        const int bh = j / D2, rem = j % D2;
        const size_t base = (size_t)bh * NC * D2 + rem;
        float run = 0.f;
#pragma unroll
        for (int c = 0; c < NC; ++c) {
            const size_t p = base + (size_t)c * D2;
            const float t2 = g_z[p]; g_z[p] = run; run += t2;
        }
    }
}

// ---------------- attention A (fp32 exact): A = mask((q.k)^2/16), den ----
__global__ __launch_bounds__(256) void attn_a_new() {
    __shared__ float qs[128 * 17];
    __shared__ float ksm[128 * 17];
    __shared__ float Zs[256];
    __shared__ float rsum[256];
    const int gx = blockIdx.x;
    const int ch = gx & (NC - 1), bh = gx / NC;
    const int b = bh / HH, h = bh % HH;
    const int tid = threadIdx.x;
    const float* qb = g_q + (size_t)(b * LLEN + ch * CH) * QKDIM + h * FDIM;
    const float* kb = g_k + (size_t)(b * LLEN + ch * CH) * QKDIM + h * FDIM;
#pragma unroll
    for (int u = 0; u < 2; ++u) {
        const int lin = tid * 2 + u;
        const int r = lin >> 2, c4 = (lin & 3) * 4;
        float4 qv = *(const float4*)(qb + (size_t)r * QKDIM + c4);
        qs[r * 17 + c4 + 0] = qv.x; qs[r * 17 + c4 + 1] = qv.y;
        qs[r * 17 + c4 + 2] = qv.z; qs[r * 17 + c4 + 3] = qv.w;
        float4 kv = *(const float4*)(kb + (size_t)r * QKDIM + c4);
        ksm[r * 17 + c4 + 0] = kv.x; ksm[r * 17 + c4 + 1] = kv.y;
        ksm[r * 17 + c4 + 2] = kv.z; ksm[r * 17 + c4 + 3] = kv.w;
    }
    Zs[tid] = g_z[((size_t)bh * NC + ch) * D2 + tid];
    __syncthreads();

    const int r = tid >> 1, cb = (tid & 1) * 64;
    float qr[16];
#pragma unroll
    for (int i = 0; i < 16; ++i) qr[i] = qs[r * 17 + i];
    float rs = 0.f;
    float* Ab = g_A + (size_t)gx * CH * CH + (size_t)r * CH + cb;
    for (int cc = 0; cc < 64; cc += 4) {
        float4 av;
        float* ap = (float*)&av;
#pragma unroll
        for (int e = 0; e < 4; ++e) {
            const int c = cb + cc + e;
            float sd = 0.f;
#pragma unroll
            for (int i = 0; i < 16; ++i) sd = fmaf(qr[i], ksm[c * 17 + i], sd);
            const float a = (c <= r) ? sd * sd * 0.0625f : 0.f;
            ap[e] = a; rs += a;
        }
        *(float4*)(Ab + cc) = av;
    }
    rsum[tid] = rs;
    __syncthreads();
    if (tid < 128) {
        float den = 0.f;
#pragma unroll
        for (int i = 0; i < 16; ++i) {
            float y = 0.f;
#pragma unroll
            for (int j = 0; j < 16; ++j) y = fmaf(Zs[i * 16 + j], qs[tid * 17 + j], y);
            den = fmaf(qs[tid * 17 + i], y, den);
        }
        g_den[(size_t)gx * CH + tid] = den * 0.25f + rsum[2 * tid] + rsum[2 * tid + 1];
    }
}

// ---------------- attention B: o = (q2 S + A v) / (den + eps) ----------
// 64(c) x 128(v) block, 256 thr, 12-stage pipeline. grid = B*H*NC*2.
__global__ __launch_bounds__(256) void attn_b_db() {
    extern __shared__ char sm[];
    const unsigned smb = sptr(sm);
    float* qsm  = (float*)(sm + 2 * GST2);          // 64*17 fp32
    float* dens = (float*)(sm + 2 * GST2 + 4352);   // 64 fp32
    const int gx = blockIdx.x;
    const int mhalf = gx & 1, base = gx >> 1;
    const int ch = base & (NC - 1), bh = base >> 4;
    const int b = bh / HH, h = bh % HH;
    const int m0 = mhalf * 64;
    const int tid = threadIdx.x, lane = tid & 31, w = tid >> 5;
    const int g = lane >> 2, t = lane & 3;
    const int mbase = (w & 1) * 32, nbase = (w >> 1) * 32;
    const int arow = tid >> 2, kseg = (tid & 3) * 8;
    const int krow = tid >> 3, nseg = (tid & 7) * 16;

    const float* qb  = g_q + (size_t)(b * LLEN + ch * CH + m0) * QKDIM + h * FDIM;
    const float* Sb  = g_S + ((size_t)bh * NC + ch) * D2 * DVDIM;
    const float* Abp = g_A + (size_t)base * CH * CH + (size_t)m0 * CH;
    const float* vb  = g_v + (size_t)(b * LLEN + ch * CH) * DMODEL + h * DVDIM;

    const unsigned offA = ((mbase + (lane & 15)) * MKS + (lane >> 4) * 8) * 2;
    const unsigned offB = ((((lane >> 3) & 1) * 8 + (lane & 7)) * KNS + nbase + ((lane >> 4) & 1) * 8) * 2;

    {   // load q tile 64x16 (4 floats/thread)
        const int r = tid >> 2, c4 = (tid & 3) * 4;
        float4 qv = *(const float4*)(qb + (size_t)r * QKDIM + c4);
        qsm[r * 17 + c4 + 0] = qv.x; qsm[r * 17 + c4 + 1] = qv.y;
        qsm[r * 17 + c4 + 2] = qv.z; qsm[r * 17 + c4 + 3] = qv.w;
    }
    if (tid < 64) dens[tid] = g_den[(size_t)base * CH + m0 + tid];

    float acc[8][4];
#pragma unroll
    for (int i = 0; i < 8; ++i) acc[i][0] = acc[i][1] = acc[i][2] = acc[i][3] = 0.f;

    float bB[16];
    float4 raf[2];
    auto loadB = [&](int s) {
        const float* r0p;
        if (s < 8) r0p = Sb + (size_t)(s * 32 + krow) * DVDIM + nseg;
        else       r0p = vb + (size_t)((s - 8) * 32 + krow) * DMODEL + nseg;
        *(float4*)&bB[0]  = *(const float4*)r0p;
        *(float4*)&bB[4]  = *(const float4*)(r0p + 4);
        *(float4*)&bB[8]  = *(const float4*)(r0p + 8);
        *(float4*)&bB[12] = *(const float4*)(r0p + 12);
    };
    auto loadA = [&](int s) {
        if (s >= 8) {
            const int c0 = (s - 8) * 32;
            raf[0] = *(const float4*)(Abp + (size_t)arow * CH + c0 + kseg);
            raf[1] = *(const float4*)(Abp + (size_t)arow * CH + c0 + kseg + 4);
        }
    };
    auto stage = [&](int bsel, int s) {
        bf16* Ah = (bf16*)(sm + bsel * GST2);
        bf16* Al = (bf16*)(sm + bsel * GST2 + ABY2);
        bf16* Bh = (bf16*)(sm + bsel * GST2 + 2 * ABY2);
        bf16* Bl = (bf16*)(sm + bsel * GST2 + 2 * ABY2 + BBYT);
        uint4 h4, l4;
        if (s < 8) {
            const int db = s * 32 + kseg;
            const float qi = qsm[arow * 17 + (db >> 4)] * 0.25f;
            const int j0 = db & 15;
            float p[8];
#pragma unroll
            for (int j = 0; j < 8; ++j) p[j] = qi * qsm[arow * 17 + j0 + j];
            split8(p, h4, l4);
        } else {
            split8((const float*)&raf[0], h4, l4);
        }
        *(uint4*)(Ah + arow * MKS + kseg) = h4;
        *(uint4*)(Al + arow * MKS + kseg) = l4;
        split8(bB, h4, l4);
        *(uint4*)(Bh + krow * KNS + nseg) = h4;
        *(uint4*)(Bl + krow * KNS + nseg) = l4;
        split8(bB + 8, h4, l4);
        *(uint4*)(Bh + krow * KNS + nseg + 8) = h4;
        *(uint4*)(Bl + krow * KNS + nseg + 8) = l4;
    };

    loadB(0);
    __syncthreads();            // qsm visible
    stage(0, 0);
    loadB(1);
    __syncthreads();
    for (int s = 0; s < 12; ++s) {
        const unsigned sb = smb + (s & 1) * GST2;
        mma_stage<32, 1280, false>(sb + offA, sb + ABY2 + offA,
                                   sb + 2 * ABY2 + offB, sb + 2 * ABY2 + BBYT + offB, acc);
        if (s + 1 < 12) {
            stage((s + 1) & 1, s + 1);
            if (s + 2 < 12) { loadB(s + 2); loadA(s + 2); }
        }
        __syncthreads();
    }

    float* ob = g_oh + (size_t)(b * LLEN + ch * CH + m0) * DMODEL + h * DVDIM;
#pragma unroll
    for (int mt = 0; mt < 2; ++mt) {
        const int r0 = mbase + mt * 16 + g;
        const float inv0 = 1.f / (dens[r0] + EPS);
        const float inv1 = 1.f / (dens[r0 + 8] + EPS);
#pragma unroll
        for (int nt = 0; nt < 4; ++nt) {
            const int col = nbase + nt * 8 + t * 2;
            const float* a4 = acc[mt * 4 + nt];
            *(float2*)(ob + (size_t)r0 * DMODEL + col)       = make_float2(a4[0] * inv0, a4[1] * inv0);
            *(float2*)(ob + (size_t)(r0 + 8) * DMODEL + col) = make_float2(a4[2] * inv1, a4[3] * inv1);
        }
    }
}

// ---------------- host pipeline ----------------
extern "C" void kernel_launch(void* const* d_in, const int* in_sizes, int n_in,
                              void* d_out, int out_size) {
    (void)in_sizes; (void)n_in; (void)out_size;
    const float* x   = (const float*)d_in[0];
    const float* Wq  = (const float*)d_in[1];
    const float* Wk  = (const float*)d_in[2];
    const float* Wv  = (const float*)d_in[3];
    const float* Wo  = (const float*)d_in[4];
    const float* lqg = (const float*)d_in[5];
    const float* lqb = (const float*)d_in[6];
    const float* lkg = (const float*)d_in[7];
    const float* lkb = (const float*)d_in[8];
    float* out = (float*)d_out;

    const int GEMM_SM = 2 * GST2;               // 55296
    const int KV_SM   = 2 * KST2 + 8704;        // 61952
    const int AB_SM   = 2 * GST2 + 4352 + 256;  // 59904
    cudaFuncSetAttribute(projqk_kernel, cudaFuncAttributeMaxDynamicSharedMemorySize, GEMM_SM);
    cudaFuncSetAttribute(proj_kernel,   cudaFuncAttributeMaxDynamicSharedMemorySize, GEMM_SM);
    cudaFuncSetAttribute(kvstate_db,    cudaFuncAttributeMaxDynamicSharedMemorySize, KV_SM);
    cudaFuncSetAttribute(attn_b_db,     cudaFuncAttributeMaxDynamicSharedMemorySize, AB_SM);

    float *vp, *ohp;
    cudaGetSymbolAddress((void**)&vp, g_v);
    cudaGetSymbolAddress((void**)&ohp, g_oh);

    projqk_kernel<<<dim3(2, 64, 2), 256, GEMM_SM>>>(x, Wq, Wk);
    proj_kernel<<<dim3(12, 64), 256, GEMM_SM>>>(x, Wv, vp, DMODEL, DMODEL);
    ln_kernel<<<(2 * NTOK) / 8, 256>>>(lqg, lqb, lkg, lkb);
    kvstate_db<<<BB * HH * NC * 4, 256, KV_SM>>>();
    {
        const int total = BB * HH * D2 * DVDIM + BB * HH * D2;
        prefix_kernel<<<(total + 255) / 256, 256>>>();
    }
    attn_a_new<<<BB * HH * NC, 256>>>();
    attn_b_db<<<BB * HH * NC * 2, 256, AB_SM>>>();
    proj_kernel<<<dim3(12, 64), 256, GEMM_SM>>>(ohp, Wo, out, DMODEL, DMODEL);
}

// round 15
// speedup vs baseline: 1.2250x; 1.2250x over previous
#include <cuda_runtime.h>
#include <cuda_bf16.h>

// ---------------- problem constants ----------------
#define BB     2
#define LLEN   2048
#define DMODEL 1536
#define HH     12
#define FDIM   16
#define DVDIM  128
#define D2     256
#define CH     128
#define NC     16
#define NTOK   4096
#define QKDIM  192
#define LN_EPS 1e-5f
#define EPS    1e-12f
#define MKS    40                 // MK tile k-stride (bf16)
#define KNS    136                // KN tile n-stride (bf16)
#define ABYT   (128 * MKS * 2)    // 10240 B per MK buffer
#define BBYT   (32 * KNS * 2)     // 8704 B per KN buffer
#define GSTR   (2 * ABYT + 2 * BBYT)  // 37888: double-buffer stride
#define KSTR   (4 * BBYT)             // 34816: kvstate buffer stride
// attn_fused layout: [2*GSTR buffers][qsm 8704][dens 512][Areg 4*2*ABYT]
#define AQSM   (2 * GSTR)
#define ADEN   (2 * GSTR + 8704)
#define AREG   (2 * GSTR + 8704 + 512)
#define ATTN_SM (AREG + 8 * ABYT)     // 166912

typedef __nv_bfloat16 bf16;

// ---------------- scratch (device globals) ----------------
__device__ float g_q [NTOK * QKDIM];
__device__ float g_k [NTOK * QKDIM];
__device__ float g_v [(size_t)NTOK * DMODEL];
__device__ float g_S [(size_t)BB * HH * NC * D2 * DVDIM];
__device__ float g_z [(size_t)BB * HH * NC * D2];
__device__ float g_oh[(size_t)NTOK * DMODEL];

// ---------------- helpers ----------------
__device__ __forceinline__ unsigned sptr(const void* p) {
    return (unsigned)__cvta_generic_to_shared(p);
}
__device__ __forceinline__ void split2(float x, float y, unsigned& h, unsigned& l) {
    __nv_bfloat162 hh = __floats2bfloat162_rn(x, y);
    float rx = x - __low2float(hh);
    float ry = y - __high2float(hh);
    __nv_bfloat162 ll = __floats2bfloat162_rn(rx, ry);
    h = *reinterpret_cast<unsigned*>(&hh);
    l = *reinterpret_cast<unsigned*>(&ll);
}
__device__ __forceinline__ void split8(const float* v, uint4& h, uint4& l) {
    split2(v[0], v[1], h.x, l.x);
    split2(v[2], v[3], h.y, l.y);
    split2(v[4], v[5], h.z, l.z);
    split2(v[6], v[7], h.w, l.w);
}
__device__ __forceinline__ void mma16(float* c, const unsigned* a, const unsigned* b) {
    asm volatile("mma.sync.aligned.m16n8k16.row.col.f32.bf16.bf16.f32 "
        "{%0,%1,%2,%3},{%4,%5,%6,%7},{%8,%9},{%0,%1,%2,%3};"
        : "+f"(c[0]), "+f"(c[1]), "+f"(c[2]), "+f"(c[3])
        : "r"(a[0]), "r"(a[1]), "r"(a[2]), "r"(a[3]), "r"(b[0]), "r"(b[1]));
}
__device__ __forceinline__ void ldsm4(uint4& r, unsigned a) {
    asm volatile("ldmatrix.sync.aligned.m8n8.x4.shared.b16 {%0,%1,%2,%3},[%4];"
        : "=r"(r.x), "=r"(r.y), "=r"(r.z), "=r"(r.w) : "r"(a));
}
__device__ __forceinline__ void ldsm4t(uint4& r, unsigned a) {
    asm volatile("ldmatrix.sync.aligned.m8n8.x4.trans.shared.b16 {%0,%1,%2,%3},[%4];"
        : "=r"(r.x), "=r"(r.y), "=r"(r.z), "=r"(r.w) : "r"(a));
}
__device__ __forceinline__ void tile3(float* acc, const uint4& ah, const uint4& al,
                                      unsigned bh0, unsigned bh1, unsigned bl0, unsigned bl1) {
    unsigned A[4] = {ah.x, ah.y, ah.z, ah.w};
    unsigned L[4] = {al.x, al.y, al.z, al.w};
    unsigned BH[2] = {bh0, bh1}, BL[2] = {bl0, bl1};
    mma16(acc, A, BH);
    mma16(acc, L, BH);
    mma16(acc, A, BL);
}

// One BK=32 stage via ldmatrix. ATR=false: A from MK (no-trans); true: A from KN (.trans).
template<bool ATR>
__device__ __forceinline__ void mma_stage(unsigned fAh, unsigned fAl,
                                          unsigned fBh, unsigned fBl,
                                          float (*acc)[4]) {
    const int aMT = ATR ? 32 : 1280;
    const int aO  = ATR ? 4352 : 32;
#pragma unroll
    for (int o = 0; o < 2; ++o) {
        uint4 ah[4], al[4], bh[2], bl[2];
#pragma unroll
        for (int mt = 0; mt < 4; ++mt) {
            if (ATR) { ldsm4t(ah[mt], fAh + o * aO + mt * aMT); ldsm4t(al[mt], fAl + o * aO + mt * aMT); }
            else     { ldsm4 (ah[mt], fAh + o * aO + mt * aMT); ldsm4 (al[mt], fAl + o * aO + mt * aMT); }
        }
#pragma unroll
        for (int p = 0; p < 2; ++p) {
            ldsm4t(bh[p], fBh + o * 4352 + p * 32);
            ldsm4t(bl[p], fBl + o * 4352 + p * 32);
        }
#pragma unroll
        for (int mt = 0; mt < 4; ++mt)
#pragma unroll
            for (int p = 0; p < 2; ++p) {
                tile3(acc[mt * 4 + 2 * p],     ah[mt], al[mt], bh[p].x, bh[p].y, bl[p].x, bl[p].y);
                tile3(acc[mt * 4 + 2 * p + 1], ah[mt], al[mt], bh[p].z, bh[p].w, bl[p].z, bl[p].w);
            }
    }
}

// ---------------- generic projection GEMM core (double-buffered) --------
__device__ __forceinline__ void gemm_core(const float* __restrict__ A,
                                          const float* __restrict__ B,
                                          float* __restrict__ C,
                                          int N, int K, int m0, int n0, char* sm) {
    const unsigned smb = sptr(sm);
    const int tid = threadIdx.x, lane = tid & 31, w = tid >> 5;
    const int g = lane >> 2, t = lane & 3;
    const int mbase = (w & 1) * 64, nbase = (w >> 1) * 32;
    const int arow = tid >> 1, kseg = (tid & 1) * 16;
    const int krow = tid >> 3, nseg = (tid & 7) * 16;
    const bool bval = (n0 + nseg) < N;
    const unsigned offA = ((mbase + (lane & 15)) * MKS + (lane >> 4) * 8) * 2;
    const unsigned offB = ((((lane >> 3) & 1) * 8 + (lane & 7)) * KNS + nbase + ((lane >> 4) & 1) * 8) * 2;

    float acc[16][4];
#pragma unroll
    for (int i = 0; i < 16; ++i) acc[i][0] = acc[i][1] = acc[i][2] = acc[i][3] = 0.f;

    float4 ra[4], rb[4];
    auto loadRegs = [&](int k0) {
#pragma unroll
        for (int i = 0; i < 4; ++i) {
            ra[i] = *(const float4*)(A + (size_t)(m0 + arow) * K + k0 + kseg + 4 * i);
            rb[i] = bval ? *(const float4*)(B + (size_t)(k0 + krow) * N + n0 + nseg + 4 * i)
                         : make_float4(0.f, 0.f, 0.f, 0.f);
        }
    };
    auto storeStage = [&](int bsel) {
        bf16* Ah = (bf16*)(sm + bsel * GSTR);
        bf16* Al = (bf16*)(sm + bsel * GSTR + ABYT);
        bf16* Bh = (bf16*)(sm + bsel * GSTR + 2 * ABYT);
        bf16* Bl = (bf16*)(sm + bsel * GSTR + 2 * ABYT + BBYT);
        uint4 h4, l4;
        split8((const float*)&ra[0], h4, l4);
        *(uint4*)(Ah + arow * MKS + kseg) = h4;     *(uint4*)(Al + arow * MKS + kseg) = l4;
        split8((const float*)&ra[2], h4, l4);
        *(uint4*)(Ah + arow * MKS + kseg + 8) = h4; *(uint4*)(Al + arow * MKS + kseg + 8) = l4;
        split8((const float*)&rb[0], h4, l4);
        *(uint4*)(Bh + krow * KNS + nseg) = h4;     *(uint4*)(Bl + krow * KNS + nseg) = l4;
        split8((const float*)&rb[2], h4, l4);
        *(uint4*)(Bh + krow * KNS + nseg + 8) = h4; *(uint4*)(Bl + krow * KNS + nseg + 8) = l4;
    };

    const int NSt = K >> 5;
    loadRegs(0);
    storeStage(0);
    loadRegs(32);
    __syncthreads();
    for (int s = 0; s < NSt; ++s) {
        const unsigned sb = smb + (s & 1) * GSTR;
        mma_stage<false>(sb + offA, sb + ABYT + offA,
                         sb + 2 * ABYT + offB, sb + 2 * ABYT + BBYT + offB, acc);
        if (s + 1 < NSt) {
            storeStage((s + 1) & 1);
            if (s + 2 < NSt) loadRegs((s + 2) * 32);
        }
        __syncthreads();
    }
#pragma unroll
    for (int mt = 0; mt < 4; ++mt) {
        const int r0 = m0 + mbase + mt * 16 + g;
#pragma unroll
        for (int nt = 0; nt < 4; ++nt) {
            const int col = n0 + nbase + nt * 8 + t * 2;
            if (col < N) {
                const float* a4 = acc[mt * 4 + nt];
                *(float2*)(C + (size_t)r0 * N + col)       = make_float2(a4[0], a4[1]);
                *(float2*)(C + (size_t)(r0 + 8) * N + col) = make_float2(a4[2], a4[3]);
            }
        }
    }
}

// Combined Wv + Wq + Wk projections in one launch (tail smoothing).
__global__ __launch_bounds__(256) void proj_all(const float* __restrict__ x,
                                                const float* __restrict__ Wq,
                                                const float* __restrict__ Wk,
                                                const float* __restrict__ Wv) {
    extern __shared__ char sm[];
    const int bx = blockIdx.x, m0 = blockIdx.y * 128;
    if (bx < 12) {
        gemm_core(x, Wv, (float*)g_v, DMODEL, DMODEL, m0, bx * 128, sm);
    } else if (bx < 14) {
        gemm_core(x, Wq, (float*)g_q, QKDIM, DMODEL, m0, (bx - 12) * 128, sm);
    } else {
        gemm_core(x, Wk, (float*)g_k, QKDIM, DMODEL, m0, (bx - 14) * 128, sm);
    }
}

__global__ __launch_bounds__(256) void proj_kernel(const float* __restrict__ A,
                                                   const float* __restrict__ B,
                                                   float* __restrict__ C, int N, int K) {
    extern __shared__ char sm[];
    gemm_core(A, B, C, N, K, blockIdx.y * 128, blockIdx.x * 128, sm);
}

// ---------------- LayerNorm over 192 dims, in place ----------------
__global__ __launch_bounds__(256) void ln_kernel(const float* __restrict__ gq,
                                                 const float* __restrict__ bq,
                                                 const float* __restrict__ gk,
                                                 const float* __restrict__ bk) {
    const int warp = (blockIdx.x * blockDim.x + threadIdx.x) >> 5;
    const int lane = threadIdx.x & 31;
    if (warp >= 2 * NTOK) return;
    const bool isq = warp < NTOK;
    float* p = isq ? (g_q + (size_t)warp * QKDIM) : (g_k + (size_t)(warp - NTOK) * QKDIM);
    const float* gg = isq ? gq : gk;
    const float* bb = isq ? bq : bk;
    float x[6]; float s = 0.f, s2 = 0.f;
#pragma unroll
    for (int i = 0; i < 6; ++i) { x[i] = p[lane + 32 * i]; s += x[i]; s2 = fmaf(x[i], x[i], s2); }
#pragma unroll
    for (int o = 16; o > 0; o >>= 1) {
        s += __shfl_xor_sync(0xffffffffu, s, o);
        s2 += __shfl_xor_sync(0xffffffffu, s2, o);
    }
    const float mu = s * (1.f / QKDIM);
    const float var = s2 * (1.f / QKDIM) - mu * mu;
    const float r = rsqrtf(var + LN_EPS);
#pragma unroll
    for (int i = 0; i < 6; ++i) {
        const int c = lane + 32 * i;
        p[c] = (x[i] - mu) * r * gg[c] + bb[c];
    }
}

// ---------------- per-chunk state: S_c = k2_c^T v_c, z_c = sum k2_c ------
__global__ __launch_bounds__(256) void kvstate_db() {
    extern __shared__ char sm[];
    const unsigned smb = sptr(sm);
    float* ksm = (float*)(sm + 2 * KSTR);     // 128*17 fp32; reused as zred
    const int gx = blockIdx.x;
    const int dhalf = gx & 1, rest = gx >> 1;
    const int ch = rest & (NC - 1), bh = rest / NC;
    const int b = bh / HH, h = bh % HH;
    const int d0 = dhalf * 128;
    const int tid = threadIdx.x, lane = tid & 31, w = tid >> 5;
    const int g = lane >> 2, t = lane & 3;
    const int mbase = (w & 1) * 64, nbase = (w >> 1) * 32;
    const int pc = tid >> 4, eg = (tid & 15) * 8;

    const float* kb = g_k + (size_t)(b * LLEN + ch * CH) * QKDIM + h * FDIM;
    const float* vb = g_v + (size_t)(b * LLEN + ch * CH) * DMODEL + h * DVDIM;

#pragma unroll
    for (int u = 0; u < 2; ++u) {
        const int lin = tid * 2 + u;
        const int r = lin >> 2, c4 = (lin & 3) * 4;
        float4 kv = *(const float4*)(kb + (size_t)r * QKDIM + c4);
        ksm[r * 17 + c4 + 0] = kv.x; ksm[r * 17 + c4 + 1] = kv.y;
        ksm[r * 17 + c4 + 2] = kv.z; ksm[r * 17 + c4 + 3] = kv.w;
    }

    const int iA = (d0 + eg) >> 4, jb = eg & 15;
    const unsigned offA = ((((lane >> 4) & 1) * 8 + (lane & 7)) * KNS + mbase + ((lane >> 3) & 1) * 8) * 2;
    const unsigned offB = ((((lane >> 3) & 1) * 8 + (lane & 7)) * KNS + nbase + ((lane >> 4) & 1) * 8) * 2;

    float acc[16][4];
#pragma unroll
    for (int i = 0; i < 16; ++i) acc[i][0] = acc[i][1] = acc[i][2] = acc[i][3] = 0.f;
    float zacc[8];
#pragma unroll
    for (int e = 0; e < 8; ++e) zacc[e] = 0.f;

    float vA[8], vB[8];
    auto loadV = [&](int c0) {
        const float* r0p = vb + (size_t)(c0 + 2 * pc) * DMODEL + eg;
        const float* r1p = vb + (size_t)(c0 + 2 * pc + 1) * DMODEL + eg;
        *(float4*)&vA[0] = *(const float4*)r0p; *(float4*)&vA[4] = *(const float4*)(r0p + 4);
        *(float4*)&vB[0] = *(const float4*)r1p; *(float4*)&vB[4] = *(const float4*)(r1p + 4);
    };
    auto stage = [&](int bsel, int c0) {
        bf16* Ah = (bf16*)(sm + bsel * KSTR);
        bf16* Al = (bf16*)(sm + bsel * KSTR + BBYT);
        bf16* Bh = (bf16*)(sm + bsel * KSTR + 2 * BBYT);
        bf16* Bl = (bf16*)(sm + bsel * KSTR + 3 * BBYT);
        const int ca = c0 + 2 * pc, cb2 = ca + 1;
        float pa[8], pb[8];
        const float kia = ksm[ca * 17 + iA] * 0.25f;
        const float kib = ksm[cb2 * 17 + iA] * 0.25f;
#pragma unroll
        for (int e = 0; e < 8; ++e) {
            pa[e] = kia * ksm[ca * 17 + jb + e];
            pb[e] = kib * ksm[cb2 * 17 + jb + e];
            zacc[e] += pa[e] + pb[e];
        }
        uint4 h4, l4;
        split8(pa, h4, l4);
        *(uint4*)(Ah + (2 * pc) * KNS + eg) = h4;     *(uint4*)(Al + (2 * pc) * KNS + eg) = l4;
        split8(pb, h4, l4);
        *(uint4*)(Ah + (2 * pc + 1) * KNS + eg) = h4; *(uint4*)(Al + (2 * pc + 1) * KNS + eg) = l4;
        split8(vA, h4, l4);
        *(uint4*)(Bh + (2 * pc) * KNS + eg) = h4;     *(uint4*)(Bl + (2 * pc) * KNS + eg) = l4;
        split8(vB, h4, l4);
        *(uint4*)(Bh + (2 * pc + 1) * KNS + eg) = h4; *(uint4*)(Bl + (2 * pc + 1) * KNS + eg) = l4;
    };

    loadV(0);
    __syncthreads();            // ksm visible
    stage(0, 0);
    loadV(32);
    __syncthreads();
    for (int s = 0; s < 4; ++s) {
        const unsigned sb = smb + (s & 1) * KSTR;
        mma_stage<true>(sb + offA, sb + BBYT + offA,
                        sb + 2 * BBYT + offB, sb + 3 * BBYT + offB, acc);
        if (s + 1 < 4) {
            stage((s + 1) & 1, (s + 1) * 32);
            if (s + 2 < 4) loadV((s + 2) * 32);
        }
        __syncthreads();
    }

    float* Sout = g_S + (((size_t)bh * NC + ch) * D2 + d0) * DVDIM;
#pragma unroll
    for (int mt = 0; mt < 4; ++mt) {
        const int r0 = mbase + mt * 16 + g;
#pragma unroll
        for (int nt = 0; nt < 4; ++nt) {
            const int col = nbase + nt * 8 + t * 2;
            const float* a4 = acc[mt * 4 + nt];
            *(float2*)(Sout + (size_t)r0 * DVDIM + col)       = make_float2(a4[0], a4[1]);
            *(float2*)(Sout + (size_t)(r0 + 8) * DVDIM + col) = make_float2(a4[2], a4[3]);
        }
    }
    // z reduction: reuse ksm region as zred[16][128]
#pragma unroll
    for (int e = 0; e < 8; ++e) ksm[pc * 128 + eg + e] = zacc[e];
    __syncthreads();
    if (tid < 128) {
        float z = 0.f;
#pragma unroll
        for (int p = 0; p < 16; ++p) z += ksm[p * 128 + tid];
        g_z[((size_t)bh * NC + ch) * D2 + d0 + tid] = z;
    }
}

// ---------------- exclusive prefix over chunks ----------------
__global__ __launch_bounds__(256) void prefix_kernel() {
    const int NS = BB * HH * D2 * DVDIM;
    const int NZ = BB * HH * D2;
    const int idx = blockIdx.x * blockDim.x + threadIdx.x;
    if (idx < NS) {
        const int bh = idx / (D2 * DVDIM);
        const int rem = idx % (D2 * DVDIM);
        const size_t base = (size_t)bh * NC * D2 * DVDIM + rem;
        float run = 0.f;
#pragma unroll
        for (int c = 0; c < NC; ++c) {
            const size_t p = base + (size_t)c * (D2 * DVDIM);
            const float t2 = g_S[p]; g_S[p] = run; run += t2;
        }
    } else if (idx < NS + NZ) {
        const int j = idx - NS;
        const int bh = j / D2, rem = j % D2;
        const size_t base = (size_t)bh * NC * D2 + rem;
        float run = 0.f;
#pragma unroll
        for (int c = 0; c < NC; ++c) {
            const size_t p = base + (size_t)c * D2;
            const float t2 = g_z[p]; g_z[p] = run; run += t2;
        }
    }
}

// ---------------- fused attention: A+den prologue, then (q2 S + A v)/den --
__global__ __launch_bounds__(256) void attn_fused() {
    extern __shared__ char sm[];
    const unsigned smb = sptr(sm);
    float* qsm  = (float*)(sm + AQSM);          // persistent 128*17 fp32
    float* dens = (float*)(sm + ADEN);          // persistent 128 fp32
    // prologue-only aliases (inside double-buffer region, dead after first stage)
    float* ksm  = (float*)(sm);                 // 128*17 fp32 = 8704
    float* Zs   = (float*)(sm + 8704);          // 256 fp32
    float* rsum = (float*)(sm + 9728);          // 256 fp32

    const int gx = blockIdx.x;
    const int ch = gx & (NC - 1), bh = gx / NC;
    const int b = bh / HH, h = bh % HH;
    const int tid = threadIdx.x, lane = tid & 31, w = tid >> 5;
    const int g = lane >> 2, t = lane & 3;
    const int mbase = (w & 1) * 64, nbase = (w >> 1) * 32;
    const int arow = tid >> 1, kseg = (tid & 1) * 16;
    const int pkr = tid >> 4, bn = (tid & 15) * 8;

    const float* qb = g_q + (size_t)(b * LLEN + ch * CH) * QKDIM + h * FDIM;
    const float* kb = g_k + (size_t)(b * LLEN + ch * CH) * QKDIM + h * FDIM;
    const float* Sb = g_S + ((size_t)bh * NC + ch) * D2 * DVDIM;
    const float* vb = g_v + (size_t)(b * LLEN + ch * CH) * DMODEL + h * DVDIM;

    const unsigned offA = ((mbase + (lane & 15)) * MKS + (lane >> 4) * 8) * 2;
    const unsigned offB = ((((lane >> 3) & 1) * 8 + (lane & 7)) * KNS + nbase + ((lane >> 4) & 1) * 8) * 2;

    // ---- prologue: load q,k,Z; compute A (into Areg, bf16 hi/lo MK tiles) + den
#pragma unroll
    for (int u = 0; u < 2; ++u) {
        const int lin = tid * 2 + u;
        const int r = lin >> 2, c4 = (lin & 3) * 4;
        float4 qv = *(const float4*)(qb + (size_t)r * QKDIM + c4);
        qsm[r * 17 + c4 + 0] = qv.x; qsm[r * 17 + c4 + 1] = qv.y;
        qsm[r * 17 + c4 + 2] = qv.z; qsm[r * 17 + c4 + 3] = qv.w;
        float4 kv = *(const float4*)(kb + (size_t)r * QKDIM + c4);
        ksm[r * 17 + c4 + 0] = kv.x; ksm[r * 17 + c4 + 1] = kv.y;
        ksm[r * 17 + c4 + 2] = kv.z; ksm[r * 17 + c4 + 3] = kv.w;
    }
    Zs[tid] = g_z[((size_t)bh * NC + ch) * D2 + tid];
    __syncthreads();
    {
        const int r = tid >> 1, cb = (tid & 1) * 64;
        float qr[16];
#pragma unroll
        for (int i = 0; i < 16; ++i) qr[i] = qsm[r * 17 + i];
        float rs = 0.f;
        for (int cc = 0; cc < 64; cc += 4) {
            float ap[4];
#pragma unroll
            for (int e = 0; e < 4; ++e) {
                const int c = cb + cc + e;
                float sd = 0.f;
#pragma unroll
                for (int i = 0; i < 16; ++i) sd = fmaf(qr[i], ksm[c * 17 + i], sd);
                const float a = (c <= r) ? sd * sd * 0.0625f : 0.f;
                ap[e] = a; rs += a;
            }
            const int c0 = cb + cc;
            const int tile = c0 >> 5, kk = c0 & 31;
            bf16* Ath = (bf16*)(sm + AREG + tile * 2 * ABYT);
            bf16* Atl = (bf16*)(sm + AREG + tile * 2 * ABYT + ABYT);
            unsigned h0, l0, h1, l1;
            split2(ap[0], ap[1], h0, l0);
            split2(ap[2], ap[3], h1, l1);
            *(uint2*)(Ath + r * MKS + kk) = make_uint2(h0, h1);
            *(uint2*)(Atl + r * MKS + kk) = make_uint2(l0, l1);
        }
        rsum[tid] = rs;
    }
    __syncthreads();
    if (tid < 128) {
        float den = 0.f;
#pragma unroll
        for (int i = 0; i < 16; ++i) {
            float y = 0.f;
#pragma unroll
            for (int j = 0; j < 16; ++j) y = fmaf(Zs[i * 16 + j], qsm[tid * 17 + j], y);
            den = fmaf(qsm[tid * 17 + i], y, den);
        }
        dens[tid] = den * 0.25f + rsum[2 * tid] + rsum[2 * tid + 1];
    }

    // ---- pipeline: 8 stages q2@S (A generated), 4 stages A(from Areg)@v
    float acc[16][4];
#pragma unroll
    for (int i = 0; i < 16; ++i) acc[i][0] = acc[i][1] = acc[i][2] = acc[i][3] = 0.f;

    float bA[8], bB[8];
    auto loadB = [&](int s) {
        const float* r0p;
        const float* r1p;
        if (s < 8) {
            r0p = Sb + (size_t)(s * 32 + 2 * pkr) * DVDIM + bn;
            r1p = Sb + (size_t)(s * 32 + 2 * pkr + 1) * DVDIM + bn;
        } else {
            r0p = vb + (size_t)((s - 8) * 32 + 2 * pkr) * DMODEL + bn;
            r1p = vb + (size_t)((s - 8) * 32 + 2 * pkr + 1) * DMODEL + bn;
        }
        *(float4*)&bA[0] = *(const float4*)r0p; *(float4*)&bA[4] = *(const float4*)(r0p + 4);
        *(float4*)&bB[0] = *(const float4*)r1p; *(float4*)&bB[4] = *(const float4*)(r1p + 4);
    };
    auto stage = [&](int bsel, int s) {
        bf16* Bh = (bf16*)(sm + bsel * GSTR + 2 * ABYT);
        bf16* Bl = (bf16*)(sm + bsel * GSTR + 2 * ABYT + BBYT);
        uint4 h4, l4;
        if (s < 8) {
            bf16* Ah = (bf16*)(sm + bsel * GSTR);
            bf16* Al = (bf16*)(sm + bsel * GSTR + ABYT);
            const int db = s * 32 + kseg;
            const float qi = qsm[arow * 17 + (db >> 4)] * 0.25f;
            float p[16];
#pragma unroll
            for (int j = 0; j < 16; ++j) p[j] = qi * qsm[arow * 17 + j];
            split8(p, h4, l4);
            *(uint4*)(Ah + arow * MKS + kseg) = h4;     *(uint4*)(Al + arow * MKS + kseg) = l4;
            split8(p + 8, h4, l4);
            *(uint4*)(Ah + arow * MKS + kseg + 8) = h4; *(uint4*)(Al + arow * MKS + kseg + 8) = l4;
        }
        split8(bA, h4, l4);
        *(uint4*)(Bh + (2 * pkr) * KNS + bn) = h4;     *(uint4*)(Bl + (2 * pkr) * KNS + bn) = l4;
        split8(bB, h4, l4);
        *(uint4*)(Bh + (2 * pkr + 1) * KNS + bn) = h4; *(uint4*)(Bl + (2 * pkr + 1) * KNS + bn) = l4;
    };

    loadB(0);
    __syncthreads();            // prologue reads done; buffers reusable
    stage(0, 0);
    loadB(1);
    __syncthreads();
    for (int s = 0; s < 12; ++s) {
        const unsigned sb = smb + (s & 1) * GSTR;
        unsigned fAh, fAl;
        if (s < 8) { fAh = sb + offA; fAl = sb + ABYT + offA; }
        else {
            fAh = smb + AREG + (s - 8) * 2 * ABYT + offA;
            fAl = fAh + ABYT;
        }
        mma_stage<false>(fAh, fAl,
                         sb + 2 * ABYT + offB, sb + 2 * ABYT + BBYT + offB, acc);
        if (s + 1 < 12) {
            stage((s + 1) & 1, s + 1);
            if (s + 2 < 12) loadB(s + 2);
        }
        __syncthreads();
    }

    float* ob = g_oh + (size_t)(b * LLEN + ch * CH) * DMODEL + h * DVDIM;
#pragma unroll
    for (int mt = 0; mt < 4; ++mt) {
        const int r0 = mbase + mt * 16 + g;
        const float inv0 = 1.f / (dens[r0] + EPS);
        const float inv1 = 1.f / (dens[r0 + 8] + EPS);
#pragma unroll
        for (int nt = 0; nt < 4; ++nt) {
            const int col = nbase + nt * 8 + t * 2;
            const float* a4 = acc[mt * 4 + nt];
            *(float2*)(ob + (size_t)r0 * DMODEL + col)       = make_float2(a4[0] * inv0, a4[1] * inv0);
            *(float2*)(ob + (size_t)(r0 + 8) * DMODEL + col) = make_float2(a4[2] * inv1, a4[3] * inv1);
        }
    }
}

// ---------------- host pipeline ----------------
extern "C" void kernel_launch(void* const* d_in, const int* in_sizes, int n_in,
                              void* d_out, int out_size) {
    (void)in_sizes; (void)n_in; (void)out_size;
    const float* x   = (const float*)d_in[0];
    const float* Wq  = (const float*)d_in[1];
    const float* Wk  = (const float*)d_in[2];
    const float* Wv  = (const float*)d_in[3];
    const float* Wo  = (const float*)d_in[4];
    const float* lqg = (const float*)d_in[5];
    const float* lqb = (const float*)d_in[6];
    const float* lkg = (const float*)d_in[7];
    const float* lkb = (const float*)d_in[8];
    float* out = (float*)d_out;

    const int GEMM_SM = 2 * GSTR;               // 75776
    const int KV_SM   = 2 * KSTR + 8704;        // 78336
    cudaFuncSetAttribute(proj_all,    cudaFuncAttributeMaxDynamicSharedMemorySize, GEMM_SM);
    cudaFuncSetAttribute(proj_kernel, cudaFuncAttributeMaxDynamicSharedMemorySize, GEMM_SM);
    cudaFuncSetAttribute(kvstate_db,  cudaFuncAttributeMaxDynamicSharedMemorySize, KV_SM);
    cudaFuncSetAttribute(attn_fused,  cudaFuncAttributeMaxDynamicSharedMemorySize, ATTN_SM);

    float *ohp;
    cudaGetSymbolAddress((void**)&ohp, g_oh);

    proj_all<<<dim3(16, 32), 256, GEMM_SM>>>(x, Wq, Wk, Wv);
    ln_kernel<<<(2 * NTOK) / 8, 256>>>(lqg, lqb, lkg, lkb);
    kvstate_db<<<BB * HH * NC * 2, 256, KV_SM>>>();
    {
        const int total = BB * HH * D2 * DVDIM + BB * HH * D2;
        prefix_kernel<<<(total + 255) / 256, 256>>>();
    }
    attn_fused<<<BB * HH * NC, 256, ATTN_SM>>>();
    proj_kernel<<<dim3(12, 32), 256, GEMM_SM>>>(ohp, Wo, out, DMODEL, DMODEL);
}